// round 8
// baseline (speedup 1.0000x reference)
#include <cuda_runtime.h>
#include <cuda_bf16.h>

typedef unsigned long long u64;

// Cross-block scratch (no allocations allowed -> __device__ globals)
__device__ float2 g_v[4][4096];   // 4 columns of the circuit unitary (natural order)
__device__ int g_flag = 0;        // sim-columns-done counter (self-resetting)
__device__ int g_done2 = 0;       // output-blocks-passed-spin counter

// ---------------- f32x2 packed helpers ----------------
__device__ __forceinline__ u64 pack2(float x, float y) {
    u64 u; asm("mov.b64 %0, {%1,%2};" : "=l"(u) : "f"(x), "f"(y)); return u;
}
__device__ __forceinline__ float2 unpack2(u64 u) {
    float2 v; asm("mov.b64 {%0,%1}, %2;" : "=f"(v.x), "=f"(v.y) : "l"(u)); return v;
}
__device__ __forceinline__ u64 swap2(u64 u) {
    float2 v = unpack2(u); return pack2(v.y, v.x);
}
__device__ __forceinline__ u64 fma2(u64 a, u64 b, u64 c) {
    u64 d; asm("fma.rn.f32x2 %0, %1, %2, %3;" : "=l"(d) : "l"(a), "l"(b), "l"(c)); return d;
}
__device__ __forceinline__ u64 mul2(u64 a, u64 b) {
    u64 d; asm("mul.rn.f32x2 %0, %1, %2;" : "=l"(d) : "l"(a), "l"(b)); return d;
}

struct Coef { u64 sx, sy, nsy, ox, oy, noy; };

// Load a prepacked Coef block (6 u64, uniform address -> LDS broadcast)
__device__ __forceinline__ Coef ldCoef(const u64* c) {
    Coef k;
    k.sx = c[0]; k.sy = c[1]; k.nsy = c[2];
    k.ox = c[3]; k.oy = c[4]; k.noy = c[5];
    return k;
}

// new = s*a + o*p (complex, 2 packed lanes): 8 f32x2 ops
__device__ __forceinline__ void cupd(u64 X, u64 Y, u64 PX, u64 PY, const Coef& c,
                                     u64& NX, u64& NY) {
    u64 nx = mul2(c.sx, X);
    nx = fma2(c.nsy, Y, nx);
    nx = fma2(c.ox, PX, nx);
    nx = fma2(c.noy, PY, nx);
    u64 ny = mul2(c.sx, Y);
    ny = fma2(c.sy, X, ny);
    ny = fma2(c.ox, PY, ny);
    ny = fma2(c.oy, PX, ny);
    NX = nx; NY = ny;
}

// ---------------- shared memory (dynamic, ~78KB) ----------------
// coef layout per gate (18 u64): [0..5] = C0 (branch 0), [6..11] = C1 (branch 1),
// [12..17] = Cp (pack-bit gate: lane0=branch0, lane1=branch1)
struct SimSmem {
    u64 coef[96 * 18];              // prepacked gate coefficients (13.8KB)
    u64 aX[2048]; u64 aY[2048];     // staging A (transpose)
    u64 bX[2048]; u64 bY[2048];     // staging B (untranspose + wire3 + CNOT perm)
};

// ---------------------------------------------------------------------------
// Indexing (512 threads, 8 amps/thread) — identical to the R7 passing kernel.
// Amp x (12 bits): x0,x1 = pair p; x2 = pack lane lam (f32x2); x3..x7 = lane
// bits t0..t4; x8..x11 = warp bits t5..t8. Wire w acts on bit 11-w.
// sigma swaps bits {0,1,2} <-> {9,10,11}; bit 8 (wire 3) is fused into the
// phase-3 gather (single-qubit gates on distinct wires commute).
// Staging float addr (natural): fnat(x) = x2 | (x3..x11 << 1) | (x0x1 << 10),
// then swizzle: fsw(f) = f ^ ((f>>5)&1)  (bank-bijective for all patterns).
// ---------------------------------------------------------------------------
__host__ __device__ constexpr int fnat(int x) {
    return ((x >> 2) & 1) | (((x >> 3) & 0x1FF) << 1) | ((x & 3) << 10);
}
__host__ __device__ constexpr int sig(int z) {
    return (z & 0x1F8) | ((z & 7) << 9) | ((z >> 9) & 7);
}
__host__ __device__ constexpr int fsw(int f) { return f ^ ((f >> 5) & 1); }
__host__ __device__ constexpr int A2f(int z) { return fsw(fnat(sig(z))); }
__host__ __device__ constexpr int A3f(int y) {
    return fsw(fnat(sig((y ^ (y >> 1)) & 0xFFF)));
}

// gate on pair bit M (in-register partner A[p^M]); cc -> C0, cc+6 -> C1
template<int M>
__device__ __forceinline__ void gate_regM(u64 AX[4], u64 AY[4], const u64* cc) {
    Coef C0 = ldCoef(cc);
    Coef C1 = ldCoef(cc + 6);
    #pragma unroll
    for (int p = 0; p < 4; p++) {
        if (p & M) continue;
        int q = p | M;
        u64 x0 = AX[p], y0 = AY[p], x1 = AX[q], y1 = AY[q];
        cupd(x0, y0, x1, y1, C0, AX[p], AY[p]);
        cupd(x1, y1, x0, y0, C1, AX[q], AY[q]);
    }
}

// gate on the pack bit (partner = other f32x2 lane); uses Cp at cc+12
__device__ __forceinline__ void gate_pack(u64 AX[4], u64 AY[4], const u64* cc) {
    Coef C = ldCoef(cc + 12);
    #pragma unroll
    for (int p = 0; p < 4; p++) {
        u64 px = swap2(AX[p]), py = swap2(AY[p]);
        cupd(AX[p], AY[p], px, py, C, AX[p], AY[p]);
    }
}

// gate on lane bit K (shfl partner lane t ^ LM); branch-selected Coef
template<int LM, int K>
__device__ __forceinline__ void gate_lane(u64 AX[4], u64 AY[4], const u64* cc, int t) {
    Coef C = ldCoef(cc + ((t >> K) & 1) * 6);
    #pragma unroll
    for (int p = 0; p < 4; p++) {
        u64 px = __shfl_xor_sync(0xffffffffu, AX[p], LM);
        u64 py = __shfl_xor_sync(0xffffffffu, AY[p], LM);
        cupd(AX[p], AY[p], px, py, C, AX[p], AY[p]);
    }
}

// ---------------------------------------------------------------------------
// Fused kernel. Blocks 0..3: one basis column each (512 thr, 8 amps/thread).
// Blocks 4..: wait, build 4x4 Gram, emit 512 outputs each.
// ---------------------------------------------------------------------------
__global__ __launch_bounds__(512, 1) void fused_kernel(
    const float* __restrict__ weights, const float* __restrict__ head_w,
    const float* __restrict__ head_b, const float* __restrict__ sb,
    float* __restrict__ out, int B, int nOut)
{
    extern __shared__ char smem_raw[];
    const int t = threadIdx.x;
    const int bid = blockIdx.x;

    if (bid < 4) {
        // ================= SIM BLOCK =================
        SimSmem* sm = (SimSmem*)smem_raw;
        if (t < 96) {
            float phi = weights[t * 3 + 0];
            float th  = weights[t * 3 + 1];
            float om  = weights[t * 3 + 2];
            float st, ct; sincosf(th * 0.5f, &st, &ct);
            float sp, cp; sincosf((phi + om) * 0.5f, &sp, &cp);
            float sd, cd; sincosf((phi - om) * 0.5f, &sd, &cd);
            const float2 u00 = make_float2( cp * ct, -sp * ct);
            const float2 u01 = make_float2(-cd * st, -sd * st);
            const float2 u10 = make_float2( cd * st, -sd * st);
            const float2 u11 = make_float2( cp * ct,  sp * ct);
            u64* c = sm->coef + t * 18;
            // C0: self=u00, off=u01 (both lanes)
            c[0]  = pack2(u00.x, u00.x); c[1]  = pack2(u00.y, u00.y);
            c[2]  = pack2(-u00.y, -u00.y);
            c[3]  = pack2(u01.x, u01.x); c[4]  = pack2(u01.y, u01.y);
            c[5]  = pack2(-u01.y, -u01.y);
            // C1: self=u11, off=u10 (both lanes)
            c[6]  = pack2(u11.x, u11.x); c[7]  = pack2(u11.y, u11.y);
            c[8]  = pack2(-u11.y, -u11.y);
            c[9]  = pack2(u10.x, u10.x); c[10] = pack2(u10.y, u10.y);
            c[11] = pack2(-u10.y, -u10.y);
            // Cp: lane0 = branch0 (u00/u01), lane1 = branch1 (u11/u10)
            c[12] = pack2(u00.x, u11.x); c[13] = pack2(u00.y, u11.y);
            c[14] = pack2(-u00.y, -u11.y);
            c[15] = pack2(u01.x, u10.x); c[16] = pack2(u01.y, u10.y);
            c[17] = pack2(-u01.y, -u10.y);
        }
        __syncthreads();

        // init |kj>: bit11 = b0 -> t8, bit10 = b1 -> t7; p=0, lam=0
        const int t_init = ((bid >> 1) & 1) * 256 + (bid & 1) * 128;
        u64 AX[4], AY[4];
        #pragma unroll
        for (int p = 0; p < 4; p++) { AX[p] = 0ull; AY[p] = 0ull; }
        if (t == t_init) AX[0] = pack2(1.0f, 0.0f);

        // layer-invariant addresses (same image as R7's scalar swizzled stores)
        const bool stSwap = (t >> 4) & 1;      // swizzle bit -> internal lane swap
        const int base2 = A2f(t << 3);
        const int base3 = A3f(t << 3);
        constexpr int cA2[4] = { A2f(0), A2f(1), A2f(2), A2f(3) };
        constexpr int A2L = A2f(4);
        constexpr int cA3[4] = { A3f(0), A3f(1), A3f(2), A3f(3) };
        constexpr int A3L = A3f(4);
        float* fAX = (float*)sm->aX; float* fAY = (float*)sm->aY;
        float* fBX = (float*)sm->bX; float* fBY = (float*)sm->bY;

        #pragma unroll 1
        for (int l = 0; l < 8; l++) {
            const u64* CG = sm->coef + l * 12 * 18;
            // ---- phase 1: wires 11..4 on bits 0..7 ----
            gate_regM<1>(AX, AY, CG + 11 * 18);        // bit 0
            gate_regM<2>(AX, AY, CG + 10 * 18);        // bit 1
            gate_pack  (AX, AY, CG + 9 * 18);          // bit 2 (pack lane)
            gate_lane<1, 0>(AX, AY, CG + 8 * 18, t);   // bit 3
            gate_lane<2, 1>(AX, AY, CG + 7 * 18, t);   // bit 4
            gate_lane<4, 2>(AX, AY, CG + 6 * 18, t);   // bit 5
            gate_lane<8, 3>(AX, AY, CG + 5 * 18, t);   // bit 6
            gate_lane<16, 4>(AX, AY, CG + 4 * 18, t);  // bit 7
            // ---- transpose: swap bits {0,1,2} <-> {9,10,11} via buffer A ----
            #pragma unroll
            for (int p = 0; p < 4; p++) {
                int s = (p << 9) | t;
                sm->aX[s] = stSwap ? swap2(AX[p]) : AX[p];
                sm->aY[s] = stSwap ? swap2(AY[p]) : AY[p];
            }
            __syncthreads();
            #pragma unroll
            for (int p = 0; p < 4; p++) {
                int a0 = base2 ^ cA2[p];
                AX[p] = pack2(fAX[a0], fAX[a0 ^ A2L]);
                AY[p] = pack2(fAY[a0], fAY[a0 ^ A2L]);
            }
            // wires 2,1,0 now on bits 0,1,2
            gate_regM<1>(AX, AY, CG + 2 * 18);
            gate_regM<2>(AX, AY, CG + 1 * 18);
            gate_pack  (AX, AY, CG + 0 * 18);
            // ---- phase 3: untranspose + wire-3 gate + CNOT perm via buffer B ----
            #pragma unroll
            for (int p = 0; p < 4; p++) {
                int s = (p << 9) | t;
                sm->bX[s] = stSwap ? swap2(AX[p]) : AX[p];
                sm->bY[s] = stSwap ? swap2(AY[p]) : AY[p];
            }
            __syncthreads();
            {
                // wire-3 gate (natural bit 8): branch = g8 = y8^y9 = t5^t6
                const int b8 = ((t >> 5) ^ (t >> 6)) & 1;
                Coef C = ldCoef(CG + 3 * 18 + b8 * 6);
                #pragma unroll
                for (int p = 0; p < 4; p++) {
                    int a0 = base3 ^ cA3[p];
                    int a1 = a0 ^ A3L;
                    u64 VX = pack2(fBX[a0], fBX[a1]);
                    u64 VY = pack2(fBY[a0], fBY[a1]);
                    u64 PX = pack2(fBX[a0 ^ 64], fBX[a1 ^ 64]);
                    u64 PY = pack2(fBY[a0 ^ 64], fBY[a1 ^ 64]);
                    cupd(VX, VY, PX, PY, C, AX[p], AY[p]);
                }
            }
        }

        // write column (natural order): amp y = (t<<3) | (lam<<2) | p
        #pragma unroll
        for (int p = 0; p < 4; p++) {
            float2 xs = unpack2(AX[p]), ys = unpack2(AY[p]);
            g_v[bid][(t << 3) | p]     = make_float2(xs.x, ys.x);
            g_v[bid][(t << 3) | 4 | p] = make_float2(xs.y, ys.y);
        }
        __threadfence();
        __syncthreads();
        if (t == 0) atomicAdd(&g_flag, 1);
    } else {
        // ================= OUTPUT BLOCK =================
        // prefetch per-sample data + sincos BEFORE the spin
        const int i = (bid - 4) * 512 + t;
        float s0 = 0.f, c0 = 1.f, s1 = 0.f, c1 = 1.f, hb = head_b[0];
        if (i < B) {
            float t0 = sb[i * 8 + 0], t1 = sb[i * 8 + 1];
            sincosf(t0 * 0.5f, &s0, &c0);
            sincosf(t1 * 0.5f, &s1, &c1);
        }
        float hw[12];
        #pragma unroll
        for (int w = 0; w < 12; w++) hw[w] = head_w[w];

        if (t == 0) {
            while (atomicAdd(&g_flag, 0) < 4) __nanosleep(64);
        }
        __syncthreads();
        __threadfence();

        // --- Gram: G[j][k] = sum_idx s(idx) v_j conj(v_k) ---
        float2 acc[4][4];
        #pragma unroll
        for (int a = 0; a < 4; a++)
            #pragma unroll
            for (int b = 0; b < 4; b++) acc[a][b] = make_float2(0.f, 0.f);

        for (int idx = t; idx < 4096; idx += 512) {
            float s = 0.f;
            #pragma unroll
            for (int w = 0; w < 12; w++)
                s += ((idx >> (11 - w)) & 1) ? -hw[w] : hw[w];
            float2 v[4];
            #pragma unroll
            for (int a = 0; a < 4; a++) v[a] = g_v[a][idx];
            #pragma unroll
            for (int a = 0; a < 4; a++)
                #pragma unroll
                for (int b = 0; b < 4; b++) {
                    float pr = v[a].x * v[b].x + v[a].y * v[b].y;
                    float pi = v[a].y * v[b].x - v[a].x * v[b].y;
                    acc[a][b].x += s * pr;
                    acc[a][b].y += s * pi;
                }
        }

        float* red = (float*)smem_raw;      // [16][32]
        float* Gs  = red + 16 * 32;         // [32]
        float* flat = reinterpret_cast<float*>(acc);
        const int lane = t & 31, warp = t >> 5;
        #pragma unroll
        for (int comp = 0; comp < 32; comp++) {
            float v = flat[comp];
            #pragma unroll
            for (int off = 16; off; off >>= 1)
                v += __shfl_down_sync(0xffffffff, v, off);
            if (lane == 0) red[warp * 32 + comp] = v;
        }
        __syncthreads();
        if (t < 32) {
            float v = 0.f;
            #pragma unroll
            for (int w = 0; w < 16; w++) v += red[w * 32 + t];
            Gs[t] = v;
        }
        __syncthreads();

        // self-resetting flags for graph replays
        if (t == 0) {
            int d = atomicAdd(&g_done2, 1);
            if (d == nOut - 1) { atomicExch(&g_flag, 0); atomicExch(&g_done2, 0); }
        }

        // --- per-sample output: out = Re(c^H G c) + bias ---
        if (i < B) {
            float2 c[4];
            c[0] = make_float2(c0 * c1, 0.f);
            c[1] = make_float2(c0 * s1, 0.f);
            c[2] = make_float2(0.f, -s0 * c1);
            c[3] = make_float2(0.f, -s0 * s1);

            float res = hb;
            #pragma unroll
            for (int jj = 0; jj < 4; jj++)
                #pragma unroll
                for (int k = 0; k < 4; k++) {
                    float ccr = c[jj].x * c[k].x + c[jj].y * c[k].y;
                    float cci = c[jj].y * c[k].x - c[jj].x * c[k].y;
                    float gx = Gs[(jj * 4 + k) * 2];
                    float gy = Gs[(jj * 4 + k) * 2 + 1];
                    res += ccr * gx - cci * gy;
                }
            out[i] = res;
        }
    }
}

extern "C" void kernel_launch(void* const* d_in, const int* in_sizes, int n_in,
                              void* d_out, int out_size) {
    const float* state_batch = (const float*)d_in[0];  // (B, 8)
    const float* weights     = (const float*)d_in[1];  // (8, 12, 3)
    const float* head_w      = (const float*)d_in[2];  // (1, 12)
    const float* head_b      = (const float*)d_in[3];  // (1,)
    float* out = (float*)d_out;
    const int B = in_sizes[0] / 8;

    const int smem_bytes = (int)sizeof(SimSmem);
    cudaFuncSetAttribute(fused_kernel, cudaFuncAttributeMaxDynamicSharedMemorySize,
                         smem_bytes);
    const int nOut = (B + 511) / 512;
    fused_kernel<<<4 + nOut, 512, smem_bytes>>>(weights, head_w, head_b,
                                                state_batch, out, B, nOut);
}